// round 17
// baseline (speedup 1.0000x reference)
#include <cuda_runtime.h>
#include <cuda_fp16.h>
#include <cstdint>
#include <math.h>

#define NN 50000
#define NE 500000
#define NE_PAD 500096           // 3907 * 128
#define EA_END 300032           // 2344 * 128 — asymmetric split (60/40)
#define LDH 136                 // k_edge2 smem leading dim (halves)
#define WBLOBH (128 * LDH)      // one weight image (halves)
#define LD1H 40                 // k_edge1 smem leading dim (halves)
#define W1H_N (3 * 32 * LD1H)   // edge1 fp16 weight blob halves (3840)

// ---------------- scratch (device globals: allocation-free) ----------------
__device__ float g_L0[NN * 32];
__device__ float g_L1[NN * 3 * 32];                         // [n][i*32+c]
__device__ __align__(16) __half g_Y[(size_t)NE_PAD * 64];   // fp16 [e][64]
__device__ __align__(16) __half g_Wb[4][WBLOBH];            // fp16 MLP weights
__device__ __align__(16) __half g_W1h[W1H_N];               // fp16 edge1 weights

// ================= helpers =================
__device__ __forceinline__ uint32_t smem_u32(const void* p) {
    uint32_t a;
    asm("{ .reg .u64 t; cvta.to.shared.u64 t, %1; cvt.u32.u64 %0, t; }" : "=r"(a) : "l"(p));
    return a;
}
__device__ __forceinline__ uint32_t pack_h2(float x, float y) {
    __half2 h = __floats2half2_rn(x, y);
    return *reinterpret_cast<uint32_t*>(&h);
}

__device__ __forceinline__ void cp16(uint32_t d, const void* s) {
    asm volatile("cp.async.cg.shared.global [%0], [%1], 16;" :: "r"(d), "l"(s) : "memory");
}
#define CP_COMMIT() asm volatile("cp.async.commit_group;" ::: "memory")
#define CP_WAIT(n)  asm volatile("cp.async.wait_group %0;" :: "n"(n) : "memory")

__device__ __forceinline__ void red2(float* p, float a, float b) {
    asm volatile("red.global.add.v2.f32 [%0], {%1, %2};" :: "l"(p), "f"(a), "f"(b) : "memory");
}
__device__ __forceinline__ void red4(float* p, float a, float b, float c, float d) {
    asm volatile("red.global.add.v4.f32 [%0], {%1, %2, %3, %4};"
                 :: "l"(p), "f"(a), "f"(b), "f"(c), "f"(d) : "memory");
}
__device__ __forceinline__ float lk(float t) { return (t >= 0.f) ? t : 0.1f * t; }

__device__ __forceinline__ void mma16(float* c, const uint32_t* a, const uint32_t* b) {
    asm volatile("mma.sync.aligned.m16n8k16.row.col.f32.f16.f16.f32 "
        "{%0,%1,%2,%3}, {%4,%5,%6,%7}, {%8,%9}, {%0,%1,%2,%3};"
        : "+f"(c[0]), "+f"(c[1]), "+f"(c[2]), "+f"(c[3])
        : "r"(a[0]), "r"(a[1]), "r"(a[2]), "r"(a[3]), "r"(b[0]), "r"(b[1]));
}

// fp16 GEMM: A[m][k], W[n][k] halves, LDH leading dim, warp tile 32x64, 8 warps.
__device__ __forceinline__ void gemm_h(const __half* __restrict__ As,
                                       const __half* __restrict__ Ws,
                                       int ksteps, int m0, int n0, int lane,
                                       float acc[2][8][4])
{
    int gr = lane >> 2, tc = lane & 3;
    const uint32_t* Ap0 = (const uint32_t*)(As + (m0 + gr) * LDH) + tc;
    const uint32_t* Ap1 = (const uint32_t*)(As + (m0 + 16 + gr) * LDH) + tc;
    const uint32_t* Wp  = (const uint32_t*)(Ws + (n0 + gr) * LDH) + tc;
    const int ROW8 = 8 * (LDH / 2);
#pragma unroll 2
    for (int ks = 0; ks < ksteps; ks++) {
        int k0 = ks * 8;
        uint32_t a[2][4], b[8][2];
        a[0][0] = Ap0[k0];
        a[0][1] = Ap0[k0 + ROW8];
        a[0][2] = Ap0[k0 + 4];
        a[0][3] = Ap0[k0 + ROW8 + 4];
        a[1][0] = Ap1[k0];
        a[1][1] = Ap1[k0 + ROW8];
        a[1][2] = Ap1[k0 + 4];
        a[1][3] = Ap1[k0 + ROW8 + 4];
#pragma unroll
        for (int ni = 0; ni < 8; ni++) {
            const uint32_t* q = Wp + ni * ROW8 + k0;
            b[ni][0] = q[0];
            b[ni][1] = q[4];
        }
#pragma unroll
        for (int mi = 0; mi < 2; mi++)
#pragma unroll
            for (int ni = 0; ni < 8; ni++) mma16(acc[mi][ni], a[mi], b[ni]);
    }
}

// ---------------- K_prep: weights -> fp16 blobs ----------------
__global__ void k_prep(const float* __restrict__ Wy000, const float* __restrict__ Wy110,
                       const float* __restrict__ Wm1, const float* __restrict__ Wm2,
                       const float* __restrict__ Wm3,
                       const float* __restrict__ W011, const float* __restrict__ W101,
                       const float* __restrict__ W111)
{
    int idx = blockIdx.x * 256 + threadIdx.x;
    if (idx < W1H_N) {
        int wi = idx / (32 * LD1H), r = idx % (32 * LD1H);
        int d = r / LD1H, c = r % LD1H;
        const float* Wsrc = (wi == 0) ? W011 : ((wi == 1) ? W101 : W111);
        g_W1h[idx] = __float2half_rn((c < 32) ? Wsrc[d * 32 + c] : 0.f);
    }
    if (idx >= WBLOBH) return;
    int n = idx / LDH, k = idx % LDH;
    float w0 = 0.f, w1 = 0.f, w2 = 0.f, w3 = 0.f;
    if (k < 64)  w0 = (k < 32) ? Wy000[n * 32 + k] : Wy110[n * 32 + (k - 32)];
    if (k < 128) { w1 = Wm1[n * 128 + k]; w2 = Wm2[n * 128 + k]; w3 = Wm3[n * 128 + k]; }
    g_Wb[0][idx] = __float2half_rn(w0);
    g_Wb[1][idx] = __float2half_rn(w1);
    g_Wb[2][idx] = __float2half_rn(w2);
    g_Wb[3][idx] = __float2half_rn(w3);
}

// ---------------- K0: node projections (64 nodes/block) ----------------
__global__ void __launch_bounds__(256) k_node(
    const float* __restrict__ xa, const float* __restrict__ xv,
    const float* __restrict__ WL0, const float* __restrict__ WL1)
{
    __shared__ float sW0t[32][132];
    __shared__ float sW1t[32][33];
    int tid = threadIdx.x;
    for (int idx = tid; idx < 4096; idx += 256) {
        int c = idx >> 7, d = idx & 127;
        sW0t[c][d] = WL0[idx];
    }
    for (int idx = tid; idx < 1024; idx += 256) {
        int c = idx >> 5, d = idx & 31;
        sW1t[c][d] = WL1[idx];
    }
    __syncthreads();

    int w = tid >> 5, lane = tid & 31;
    const float4* wv = (const float4*)&sW0t[lane][0];

#pragma unroll 2
    for (int it = 0; it < 8; it++) {
        int n = blockIdx.x * 64 + it * 8 + w;
        if (n >= NN) return;

        const float4* x4 = (const float4*)(xa + n * 128);
        float acc = 0.f;
#pragma unroll 8
        for (int d4 = 0; d4 < 32; d4++) {
            float4 a = __ldg(x4 + d4), b = wv[d4];
            acc += a.x * b.x + a.y * b.y + a.z * b.z + a.w * b.w;
        }
        g_L0[n * 32 + lane] = acc;

        const float* xvp = xv + n * 96;
        float a0 = 0.f, a1 = 0.f, a2 = 0.f;
#pragma unroll 8
        for (int d = 0; d < 32; d++) {
            float wd = sW1t[lane][d];
            a0 += __ldg(xvp + 3 * d)     * wd;
            a1 += __ldg(xvp + 3 * d + 1) * wd;
            a2 += __ldg(xvp + 3 * d + 2) * wd;
        }
        g_L1[n * 96 +      lane] = a0;
        g_L1[n * 96 + 32 + lane] = a1;
        g_L1[n * 96 + 64 + lane] = a2;
    }
}

// ---------------- K1: edge light path (frozen R12 config) ----------------
__global__ void __launch_bounds__(256, 2) k_edge1(
    const float* __restrict__ rij, const int* __restrict__ src,
    const int* __restrict__ dst,
    const float* __restrict__ Wenc, const float* __restrict__ benc,
    float* __restrict__ Bv, int e_base, int e_end)
{
    extern __shared__ __align__(16) char s1c[];
    __half* sH   = (__half*)s1c;                  // 4 x 128 x LD1H
    __half* sWh  = (__half*)(s1c + 40960);
    float*  s_rs = (float*)(s1c + 48640);
    float*  s_ek = (float*)(s1c + 50688);
    float*  sP   = (float*)s1c;                   // reuse after GEMMs
    __shared__ float sWe[8 * 32];
    __shared__ float sbe[32];
    __shared__ int   s_src[128];
    __shared__ int   s_dst[128];

    int tid = threadIdx.x, wid = tid >> 5, lane = tid & 31;
    int e0 = e_base + blockIdx.x * 128;

    {
        uint32_t uSW = smem_u32(sWh);
        for (int idx = tid; idx < W1H_N * 2 / 16; idx += 256)
            cp16(uSW + (uint32_t)(idx * 16), (const char*)g_W1h + idx * 16);
        CP_COMMIT();
    }
    for (int idx = tid; idx < 256; idx += 256) {
        int c = idx >> 3, k = idx & 7;
        sWe[k * 32 + c] = Wenc[idx];
    }
    if (tid < 32) sbe[tid] = benc[tid];
    if (tid < 128) s_src[tid] = (e0 + tid < e_end) ? src[e0 + tid] : -1;

    if (tid < 128) {
        int e = e0 + tid;
        float sx = 0.f, sy = 0.f, sz = 0.f;
        if (e < e_end) {
            float rx = rij[3 * e], ry = rij[3 * e + 1], rz = rij[3 * e + 2];
            float rn = sqrtf(rx * rx + ry * ry + rz * rz);
#pragma unroll
            for (int k = 0; k < 8; k++) {
                float t = (rn - (5.0f / 7.0f) * (float)k) * 1.6f;
                s_ek[tid * 8 + k] = __expf(-t * t);
            }
            float n14 = 1.4f * rn;
            float em = __expf(-2.f * n14);
            float sq = __fdividef(1.f - em, (1.f + em) * fmaxf(n14, 1e-6f));
            sx = 1.4f * rx * sq; sy = 1.4f * ry * sq; sz = 1.4f * rz * sq;
            s_dst[tid] = dst[e];
        } else {
#pragma unroll
            for (int k = 0; k < 8; k++) s_ek[tid * 8 + k] = 0.f;
            s_dst[tid] = 0;
        }
        s_rs[tid * 4]     = sx;
        s_rs[tid * 4 + 1] = sy;
        s_rs[tid * 4 + 2] = sz;
    }
    CP_WAIT(0);
    __syncthreads();

    __half* sY0 = sH;
    __half* sGx = sH + 128 * LD1H;
    __half* sGy = sH + 2 * 128 * LD1H;
    __half* sGz = sH + 3 * 128 * LD1H;
    for (int it = 0; it < 16; it++) {
        int el = it * 8 + wid;
        int e  = e0 + el;
        bool ok = (e < e_end);
        float sx = s_rs[el * 4], sy = s_rs[el * 4 + 1], sz = s_rs[el * 4 + 2];

        float g = sbe[lane];
#pragma unroll
        for (int k = 0; k < 8; k++)
            g += s_ek[el * 8 + k] * sWe[k * 32 + lane];

        int dn = s_dst[el];
        float la  = g_L0[dn * 32 + lane];
        float lvx = g_L1[dn * 96 +      lane];
        float lvy = g_L1[dn * 96 + 32 + lane];
        float lvz = g_L1[dn * 96 + 64 + lane];

        __half y0 = __float2half_rn(ok ? la * g : 0.f);
        __half gx = __float2half_rn(ok ? g * lvx : 0.f);
        __half gy = __float2half_rn(ok ? g * lvy : 0.f);
        __half gz = __float2half_rn(ok ? g * lvz : 0.f);

        if (ok) {
            g_Y[(size_t)e * 64 + lane]      = y0;
            g_Y[(size_t)e * 64 + 32 + lane] = __float2half_rn((lvx * sx + lvy * sy + lvz * sz) * g);
        }
        sY0[el * LD1H + lane] = y0;
        sGx[el * LD1H + lane] = gx;
        sGy[el * LD1H + lane] = gy;
        sGz[el * LD1H + lane] = gz;
    }
    __syncthreads();

    int cg = wid & 1, rg = wid >> 1;
    int n0 = cg * 16;
    int ar = lane >> 2, ac = lane & 3;
    const int ROW8H = 8 * (LD1H / 2);

    float P[2][2][4][3];

#pragma unroll
    for (int pass = 0; pass < 2; pass++) {
        int m0 = pass * 64 + rg * 16;
        float q[2][4], u[3][2][4], vv[3][2][4];
#pragma unroll
        for (int ni = 0; ni < 2; ni++)
#pragma unroll
            for (int j = 0; j < 4; j++) {
                q[ni][j] = 0.f;
#pragma unroll
                for (int i = 0; i < 3; i++) { u[i][ni][j] = 0.f; vv[i][ni][j] = 0.f; }
            }

        const uint32_t* Ay  = (const uint32_t*)(sY0 + (m0 + ar) * LD1H) + ac;
        const uint32_t* Agx = (const uint32_t*)(sGx + (m0 + ar) * LD1H) + ac;
        const uint32_t* Agy = (const uint32_t*)(sGy + (m0 + ar) * LD1H) + ac;
        const uint32_t* Agz = (const uint32_t*)(sGz + (m0 + ar) * LD1H) + ac;
        const uint32_t* B0 = (const uint32_t*)(sWh + 0 * 32 * LD1H + (n0 + ar) * LD1H) + ac;
        const uint32_t* B1 = (const uint32_t*)(sWh + 1 * 32 * LD1H + (n0 + ar) * LD1H) + ac;
        const uint32_t* B2 = (const uint32_t*)(sWh + 2 * 32 * LD1H + (n0 + ar) * LD1H) + ac;

#pragma unroll
        for (int ks = 0; ks < 2; ks++) {
            int k0 = ks * 8;
            uint32_t ay[4], ag[3][4];
            ay[0] = Ay[k0];
            ay[1] = Ay[k0 + ROW8H];
            ay[2] = Ay[k0 + 4];
            ay[3] = Ay[k0 + ROW8H + 4];
            const uint32_t* Ags[3] = {Agx, Agy, Agz};
#pragma unroll
            for (int i = 0; i < 3; i++) {
                ag[i][0] = Ags[i][k0];
                ag[i][1] = Ags[i][k0 + ROW8H];
                ag[i][2] = Ags[i][k0 + 4];
                ag[i][3] = Ags[i][k0 + ROW8H + 4];
            }
            uint32_t b0[2][2], b1[2][2], b2[2][2];
#pragma unroll
            for (int ni = 0; ni < 2; ni++) {
                b0[ni][0] = B0[ni * ROW8H + k0];
                b0[ni][1] = B0[ni * ROW8H + k0 + 4];
                b1[ni][0] = B1[ni * ROW8H + k0];
                b1[ni][1] = B1[ni * ROW8H + k0 + 4];
                b2[ni][0] = B2[ni * ROW8H + k0];
                b2[ni][1] = B2[ni * ROW8H + k0 + 4];
            }
#pragma unroll
            for (int ni = 0; ni < 2; ni++) {
                mma16(q[ni], ay, b0[ni]);
#pragma unroll
                for (int i = 0; i < 3; i++) {
                    mma16(u[i][ni],  ag[i], b1[ni]);
                    mma16(vv[i][ni], ag[i], b2[ni]);
                }
            }
        }

        int r0 = m0 + ar, r1 = r0 + 8;
        float rx0 = s_rs[r0 * 4], ry0 = s_rs[r0 * 4 + 1], rz0 = s_rs[r0 * 4 + 2];
        float rx1 = s_rs[r1 * 4], ry1 = s_rs[r1 * 4 + 1], rz1 = s_rs[r1 * 4 + 2];
#pragma unroll
        for (int ni = 0; ni < 2; ni++)
#pragma unroll
            for (int j = 0; j < 4; j++) {
                float rx = (j < 2) ? rx0 : rx1;
                float ry = (j < 2) ? ry0 : ry1;
                float rz = (j < 2) ? rz0 : rz1;
                float qq = q[ni][j];
                P[pass][ni][j][0] = 0.1f * (qq * rx + u[0][ni][j] + vv[1][ni][j] * rz - vv[2][ni][j] * ry);
                P[pass][ni][j][1] = 0.1f * (qq * ry + u[1][ni][j] + vv[2][ni][j] * rx - vv[0][ni][j] * rz);
                P[pass][ni][j][2] = 0.1f * (qq * rz + u[2][ni][j] + vv[0][ni][j] * ry - vv[1][ni][j] * rx);
            }
    }
    __syncthreads();

#pragma unroll
    for (int pass = 0; pass < 2; pass++)
#pragma unroll
        for (int ni = 0; ni < 2; ni++)
#pragma unroll
            for (int j = 0; j < 4; j++) {
                int row = pass * 64 + rg * 16 + ar + ((j >= 2) ? 8 : 0);
                int col = n0 + ni * 8 + 2 * ac + (j & 1);
                float* p = sP + row * 96 + col * 3;
                p[0] = P[pass][ni][j][0];
                p[1] = P[pass][ni][j][1];
                p[2] = P[pass][ni][j][2];
            }
    __syncthreads();

    const float4* sP4 = (const float4*)sP;
    for (int it = 0; it < 16; it++) {
        int el = it * 8 + wid;
        int sn = s_src[el];
        if (sn >= 0 && lane < 24) {
            float4 v = sP4[el * 24 + lane];
            red4(Bv + (size_t)sn * 96 + lane * 4, v.x, v.y, v.z, v.w);
        }
    }
}

// ---------------- K2: fp16 mma MLP chain, ping-pong A buffers (8 warps) ----------------
__global__ void __launch_bounds__(256)
k_edge2(const float* __restrict__ bm1, const float* __restrict__ bm2,
        const int* __restrict__ src, float* __restrict__ Ba, int e_base, int e_end)
{
    extern __shared__ __align__(16) __half smh[];
    __half* As0 = smh;
    __half* As1 = smh + WBLOBH;
    __half* W0  = smh + 2 * WBLOBH;
    __half* W1  = smh + 3 * WBLOBH;
    __shared__ float s_b1[128], s_b2[128];
    __shared__ int s_src[128];

    int tid = threadIdx.x, wid = tid >> 5, lane = tid & 31;
    int m0 = (wid >> 1) * 32, n0 = (wid & 1) * 64;
    int gr = lane >> 2, tc = lane & 3;
    int e0 = e_base + blockIdx.x * 128;

    if (tid < 128) {
        s_b1[tid] = bm1[tid];
        s_b2[tid] = bm2[tid];
        int e = e0 + tid;
        s_src[tid] = (e < e_end) ? src[e] : -1;
    }

    uint32_t uA0 = smem_u32(As0);
    uint32_t uW0 = smem_u32(W0);
    uint32_t uW1 = smem_u32(W1);

    for (int idx = tid; idx < 1024; idx += 256) {
        int m = idx >> 3, c = idx & 7;
        cp16(uA0 + (uint32_t)(m * (LDH * 2) + c * 16),
             (const char*)(g_Y + (size_t)(e0 + m) * 64) + c * 16);
    }
    for (int idx = tid; idx < 2176; idx += 256)
        cp16(uW0 + (uint32_t)(idx * 16), (const char*)g_Wb[0] + idx * 16);
    CP_COMMIT();
    for (int idx = tid; idx < 2176; idx += 256)
        cp16(uW1 + (uint32_t)(idx * 16), (const char*)g_Wb[1] + idx * 16);
    CP_COMMIT();
    CP_WAIT(1);
    __syncthreads();

    float acc[2][8][4];
#pragma unroll
    for (int mi = 0; mi < 2; mi++)
#pragma unroll
        for (int ni = 0; ni < 8; ni++)
#pragma unroll
            for (int j = 0; j < 4; j++) acc[mi][ni][j] = 0.f;

    // ---- GEMM1: psi0 = Y(As0) @ Wcat(W0)^T ; epilogue -> As1 ----
    gemm_h(As0, W0, 4, m0, n0, lane, acc);

    float psi[2][8][4];
#pragma unroll
    for (int mi = 0; mi < 2; mi++)
#pragma unroll
        for (int ni = 0; ni < 8; ni++)
#pragma unroll
            for (int j = 0; j < 4; j++) psi[mi][ni][j] = acc[mi][ni][j];

#pragma unroll
    for (int mi = 0; mi < 2; mi++)
#pragma unroll
        for (int ni = 0; ni < 8; ni++) {
            int row = m0 + mi * 16 + gr;
            int cu = (n0 + ni * 8) / 2 + tc;
            ((uint32_t*)(As1 + row * LDH))[cu]       = pack_h2(acc[mi][ni][0], acc[mi][ni][1]);
            ((uint32_t*)(As1 + (row + 8) * LDH))[cu] = pack_h2(acc[mi][ni][2], acc[mi][ni][3]);
        }
    __syncthreads();
    for (int idx = tid; idx < 2176; idx += 256)
        cp16(uW0 + (uint32_t)(idx * 16), (const char*)g_Wb[2] + idx * 16);
    CP_COMMIT();
    CP_WAIT(1);

    // ---- GEMM2: h1 = leaky(psi0(As1) @ Wm1(W1)^T + b1) ; epilogue -> As0 ----
#pragma unroll
    for (int mi = 0; mi < 2; mi++)
#pragma unroll
        for (int ni = 0; ni < 8; ni++)
#pragma unroll
            for (int j = 0; j < 4; j++) acc[mi][ni][j] = 0.f;
    gemm_h(As1, W1, 8, m0, n0, lane, acc);
#pragma unroll
    for (int mi = 0; mi < 2; mi++)
#pragma unroll
        for (int ni = 0; ni < 8; ni++) {
            int row = m0 + mi * 16 + gr;
            int col = n0 + ni * 8 + 2 * tc;
            int cu = col >> 1;
            float2 bb = *(const float2*)(s_b1 + col);
            ((uint32_t*)(As0 + row * LDH))[cu] =
                pack_h2(lk(acc[mi][ni][0] + bb.x), lk(acc[mi][ni][1] + bb.y));
            ((uint32_t*)(As0 + (row + 8) * LDH))[cu] =
                pack_h2(lk(acc[mi][ni][2] + bb.x), lk(acc[mi][ni][3] + bb.y));
        }
    __syncthreads();
    for (int idx = tid; idx < 2176; idx += 256)
        cp16(uW1 + (uint32_t)(idx * 16), (const char*)g_Wb[3] + idx * 16);
    CP_COMMIT();
    CP_WAIT(1);

    // ---- GEMM3: h2 = leaky(h1(As0) @ Wm2(W0)^T + b2) ; epilogue -> As1 ----
#pragma unroll
    for (int mi = 0; mi < 2; mi++)
#pragma unroll
        for (int ni = 0; ni < 8; ni++)
#pragma unroll
            for (int j = 0; j < 4; j++) acc[mi][ni][j] = 0.f;
    gemm_h(As0, W0, 8, m0, n0, lane, acc);
#pragma unroll
    for (int mi = 0; mi < 2; mi++)
#pragma unroll
        for (int ni = 0; ni < 8; ni++) {
            int row = m0 + mi * 16 + gr;
            int col = n0 + ni * 8 + 2 * tc;
            int cu = col >> 1;
            float2 bb = *(const float2*)(s_b2 + col);
            ((uint32_t*)(As1 + row * LDH))[cu] =
                pack_h2(lk(acc[mi][ni][0] + bb.x), lk(acc[mi][ni][1] + bb.y));
            ((uint32_t*)(As1 + (row + 8) * LDH))[cu] =
                pack_h2(lk(acc[mi][ni][2] + bb.x), lk(acc[mi][ni][3] + bb.y));
        }
    CP_WAIT(0);
    __syncthreads();

    // ---- GEMM4: psi_a = psi0 + h2(As1) @ Wm3(W1)^T ; scatter ----
#pragma unroll
    for (int mi = 0; mi < 2; mi++)
#pragma unroll
        for (int ni = 0; ni < 8; ni++)
#pragma unroll
            for (int j = 0; j < 4; j++) acc[mi][ni][j] = psi[mi][ni][j];
    gemm_h(As1, W1, 8, m0, n0, lane, acc);

#pragma unroll
    for (int mi = 0; mi < 2; mi++) {
        int row = m0 + mi * 16 + gr;
        int sn0 = s_src[row];
        int sn1 = s_src[row + 8];
#pragma unroll
        for (int ni = 0; ni < 8; ni++) {
            int col = n0 + ni * 8 + 2 * tc;
            if (sn0 >= 0)
                red2(Ba + (size_t)sn0 * 128 + col, 0.1f * acc[mi][ni][0], 0.1f * acc[mi][ni][1]);
            if (sn1 >= 0)
                red2(Ba + (size_t)sn1 * 128 + col, 0.1f * acc[mi][ni][2], 0.1f * acc[mi][ni][3]);
        }
    }
}

// ---------------- launch (asymmetric two-stream pipeline) ----------------
extern "C" void kernel_launch(void* const* d_in, const int* in_sizes, int n_in,
                              void* d_out, int out_size)
{
    const float* x_a   = (const float*)d_in[0];
    const float* x_v   = (const float*)d_in[1];
    const float* r_ij  = (const float*)d_in[2];
    const int*   src   = (const int*)  d_in[3];
    const int*   dst   = (const int*)  d_in[4];
    const float* WL0   = (const float*)d_in[5];
    const float* WL1   = (const float*)d_in[6];
    const float* Wenc  = (const float*)d_in[7];
    const float* benc  = (const float*)d_in[8];
    const float* Wy000 = (const float*)d_in[9];
    const float* Wy110 = (const float*)d_in[10];
    const float* Wy011 = (const float*)d_in[11];
    const float* Wy101 = (const float*)d_in[12];
    const float* Wy111 = (const float*)d_in[13];
    const float* Wm1   = (const float*)d_in[14];
    const float* bm1   = (const float*)d_in[15];
    const float* Wm2   = (const float*)d_in[16];
    const float* bm2   = (const float*)d_in[17];
    const float* Wm3   = (const float*)d_in[18];
    float* out = (float*)d_out;
    float* Bv  = out + (size_t)NN * 128;

    static cudaStream_t sA = nullptr, sB = nullptr;
    static cudaEvent_t evRoot, evM, evN, evPd, evDoneB;
    if (!sA) {
        int loPri, hiPri;
        cudaDeviceGetStreamPriorityRange(&loPri, &hiPri);
        cudaStreamCreateWithPriority(&sA, cudaStreamNonBlocking, loPri);
        cudaStreamCreateWithPriority(&sB, cudaStreamNonBlocking, hiPri);
        cudaEventCreateWithFlags(&evRoot,  cudaEventDisableTiming);
        cudaEventCreateWithFlags(&evM,     cudaEventDisableTiming);
        cudaEventCreateWithFlags(&evN,     cudaEventDisableTiming);
        cudaEventCreateWithFlags(&evPd,    cudaEventDisableTiming);
        cudaEventCreateWithFlags(&evDoneB, cudaEventDisableTiming);

        int smem1 = 54784;
        int smem2 = 4 * WBLOBH * (int)sizeof(__half);
        cudaFuncSetAttribute(k_edge1, cudaFuncAttributeMaxDynamicSharedMemorySize, smem1);
        cudaFuncSetAttribute(k_edge2, cudaFuncAttributeMaxDynamicSharedMemorySize, smem2);
    }
    const int smem1 = 54784;
    const int smem2 = 4 * WBLOBH * (int)sizeof(__half);   // 139,264

    // fork
    cudaEventRecord(evRoot, 0);
    cudaStreamWaitEvent(sA, evRoot, 0);
    cudaStreamWaitEvent(sB, evRoot, 0);

    // head: memset (s0) || prep (sA) || node (sB)
    cudaMemsetAsync(out, 0, (size_t)out_size * sizeof(float), 0);
    cudaEventRecord(evM, 0);
    k_prep<<<(WBLOBH + 255) / 256, 256, 0, sA>>>(Wy000, Wy110, Wm1, Wm2, Wm3,
                                                 Wy011, Wy101, Wy111);
    cudaEventRecord(evPd, sA);
    k_node<<<(NN + 63) / 64, 256, 0, sB>>>(x_a, x_v, WL0, WL1);
    cudaEventRecord(evN, sB);

    // pipeline A on s0 (60%): edge1_A -> edge2_A
    cudaStreamWaitEvent(0, evN, 0);
    cudaStreamWaitEvent(0, evPd, 0);
    k_edge1<<<EA_END / 128, 256, smem1, 0>>>(r_ij, src, dst, Wenc, benc, Bv, 0, EA_END);
    k_edge2<<<EA_END / 128, 256, smem2, 0>>>(bm1, bm2, src, out, 0, EA_END);

    // pipeline B on sB (40%, high priority): edge1_B -> edge2_B — B drains edge1
    // early, so edge2_B overlaps edge1_A's tail; later edge2_A overlaps edge2_B.
    cudaStreamWaitEvent(sB, evM, 0);
    cudaStreamWaitEvent(sB, evPd, 0);
    k_edge1<<<(NE - EA_END + 127) / 128, 256, smem1, sB>>>(r_ij, src, dst, Wenc, benc,
                                                           Bv, EA_END, NE);
    k_edge2<<<(NE - EA_END + 127) / 128, 256, smem2, sB>>>(bm1, bm2, src, out, EA_END, NE);
    cudaEventRecord(evDoneB, sB);

    // join B back into the capture-origin stream
    cudaStreamWaitEvent(0, evDoneB, 0);
}